// round 2
// baseline (speedup 1.0000x reference)
#include <cuda_runtime.h>
#include <cstdint>

// LSTM: B=32, T=1024, I=512, H=512, gates G=4H=2048
// out layout: outs[B][T][H] (16777216 floats) | h_T[B][H] | c_T[B][H]

#define NB 32
#define NT 1024
#define NI 512
#define NH 512
#define NG 2048

#define SCAN_BLOCKS 128
#define SCAN_THREADS 256

// ---------------- device scratch (no allocations allowed) ----------------
__device__ float g_xg[(size_t)NT * NB * NG];   // [t][b][g]  (268 MB)
__device__ float g_h[2][NB * NH];              // double-buffered hidden state
__device__ unsigned g_bar;                     // monotonic barrier counter

// ---------------- f32x2 helpers ----------------
__device__ __forceinline__ unsigned long long pk2(float lo, float hi) {
    unsigned long long r;
    asm("mov.b64 %0, {%1, %2};" : "=l"(r) : "f"(lo), "f"(hi));
    return r;
}
__device__ __forceinline__ void fma2(unsigned long long& acc,
                                     unsigned long long a, unsigned long long b) {
    asm("fma.rn.f32x2 %0, %1, %2, %0;" : "+l"(acc) : "l"(a), "l"(b));
}
__device__ __forceinline__ float2 upk(unsigned long long v) {
    float2 f;
    asm("mov.b64 {%0, %1}, %2;" : "=f"(f.x), "=f"(f.y) : "l"(v));
    return f;
}
__device__ __forceinline__ float sigf(float x) {
    return 1.0f / (1.0f + __expf(-x));
}

// ---------------- init: zero h0 and barrier (must run every replay) ----------------
__global__ void k_init() {
    int t = threadIdx.x + blockIdx.x * blockDim.x;
    if (t == 0) g_bar = 0u;
    for (int i = t; i < NB * NH; i += gridDim.x * blockDim.x) {
        g_h[0][i] = 0.0f;
        g_h[1][i] = 0.0f;
    }
}

// ---------------- GEMM: xg[t][b][g] = x[b][t][:] . W_ih[g][:] + b_ih[g] + b_hh[g] ----------------
// M = B*T = 32768 (rows of x, m = b*T + t), N = 2048, K = 512.
// 128x128 block tile, KT=16, 256 threads, 8x8 thread tile, f32x2 accumulation.
__global__ void __launch_bounds__(256) k_gemm(const float* __restrict__ X,
                                              const float* __restrict__ Wih,
                                              const float* __restrict__ bih,
                                              const float* __restrict__ bhh) {
    __shared__ float As[2][16][132];
    __shared__ float Bs[2][16][132];

    const int tid = threadIdx.x;
    const int m0 = blockIdx.y * 128;
    const int n0 = blockIdx.x * 128;
    const int tx = tid & 15;       // n sub-tile
    const int ty = tid >> 4;       // m sub-tile
    const int lr = tid >> 2;       // 0..63 load row base
    const int lq = tid & 3;        // 0..3  load quad

    unsigned long long acc[8][4];
#pragma unroll
    for (int i = 0; i < 8; i++)
#pragma unroll
        for (int j = 0; j < 4; j++) acc[i][j] = 0ull;

    float4 aR[2], bR[2];

    // prefetch tile 0
#pragma unroll
    for (int l = 0; l < 2; l++) {
        aR[l] = __ldg((const float4*)(X   + (size_t)(m0 + lr + 64 * l) * NI + 4 * lq));
        bR[l] = __ldg((const float4*)(Wih + (size_t)(n0 + lr + 64 * l) * NI + 4 * lq));
    }

    int buf = 0;
    for (int it = 0; it < 32; it++) {
        // store current tile (transposed: [k][m])
#pragma unroll
        for (int l = 0; l < 2; l++) {
            const float* av = (const float*)&aR[l];
            const float* bv = (const float*)&bR[l];
#pragma unroll
            for (int i = 0; i < 4; i++) {
                As[buf][4 * lq + i][lr + 64 * l] = av[i];
                Bs[buf][4 * lq + i][lr + 64 * l] = bv[i];
            }
        }
        __syncthreads();

        if (it < 31) {
            const int k0 = (it + 1) * 16;
#pragma unroll
            for (int l = 0; l < 2; l++) {
                aR[l] = __ldg((const float4*)(X   + (size_t)(m0 + lr + 64 * l) * NI + k0 + 4 * lq));
                bR[l] = __ldg((const float4*)(Wih + (size_t)(n0 + lr + 64 * l) * NI + k0 + 4 * lq));
            }
        }

#pragma unroll
        for (int k = 0; k < 16; k++) {
            float4 a0 = *(const float4*)&As[buf][k][ty * 8];
            float4 a1 = *(const float4*)&As[buf][k][ty * 8 + 4];
            float4 b0 = *(const float4*)&Bs[buf][k][tx * 8];
            float4 b1 = *(const float4*)&Bs[buf][k][tx * 8 + 4];
            unsigned long long bb[4] = {pk2(b0.x, b0.y), pk2(b0.z, b0.w),
                                        pk2(b1.x, b1.y), pk2(b1.z, b1.w)};
            float av[8] = {a0.x, a0.y, a0.z, a0.w, a1.x, a1.y, a1.z, a1.w};
#pragma unroll
            for (int i = 0; i < 8; i++) {
                unsigned long long aa = pk2(av[i], av[i]);
#pragma unroll
                for (int j = 0; j < 4; j++) fma2(acc[i][j], aa, bb[j]);
            }
        }
        buf ^= 1;
        __syncthreads();
    }

    // epilogue: bias add + scatter to xg[t][b][g]
    const int nb = n0 + tx * 8;
    float bias[8];
#pragma unroll
    for (int j = 0; j < 8; j++) bias[j] = __ldg(bih + nb + j) + __ldg(bhh + nb + j);

#pragma unroll
    for (int i = 0; i < 8; i++) {
        const int m = m0 + ty * 8 + i;
        const int t = m & (NT - 1);
        const int b = m >> 10;
        float* orow = g_xg + ((size_t)t * NB + b) * NG + nb;
#pragma unroll
        for (int j2 = 0; j2 < 4; j2++) {
            float2 v = upk(acc[i][j2]);
            v.x += bias[2 * j2];
            v.y += bias[2 * j2 + 1];
            *(float2*)(orow + 2 * j2) = v;
        }
    }
}

// ---------------- persistent scan kernel ----------------
// 128 blocks; block bid owns hidden units j0 = bid*4 .. +3, i.e. the 16 gate rows
// grow(gl) = (gl%4)*512 + j0 + gl/4  (gl = jj*4 + q).
// Per step: load h to smem, 8 warps each do a K-chunk of 64 over all 512
// block-outputs (4b x 4g register tiles, f32x2), reduce via smem, finalize the
// LSTM cell locally (c in registers), publish h to the other global buffer,
// one chip-wide barrier.
__global__ void __launch_bounds__(SCAN_THREADS, 1) k_scan(float* __restrict__ out,
                                                          const float* __restrict__ Whh) {
    extern __shared__ float sm[];
    float* sW   = sm;                 // [16][514]
    float* sH   = sW + 16 * 514;      // [32][514]
    float* sRed = sH + 32 * 514;      // [8][512]

    const int tid = threadIdx.x;
    const int bid = blockIdx.x;
    const int j0 = bid * 4;

    // load the block's 16 W_hh rows once
    for (int idx = tid; idx < 16 * 512; idx += SCAN_THREADS) {
        const int gl = idx >> 9;
        const int k  = idx & 511;
        const int grow = (gl & 3) * 512 + j0 + (gl >> 2);
        sW[gl * 514 + k] = __ldg(Whh + (size_t)grow * NH + k);
    }

    // dot-phase roles
    const int w    = tid >> 5;        // k-chunk (warp)
    const int lane = tid & 31;
    const int bg   = lane & 7;        // b group: b = 4*bg + ib
    const int gg   = lane >> 3;       // g group: gl = 4*gg + u

    // finalize roles (tid < 128)
    const int fb  = tid & 31;
    const int fjj = tid >> 5;         // 0..3 for tid<128

    float creg = 0.0f;
    __syncthreads();

    for (int t = 0; t < NT; t++) {
        const int cur = t & 1;
        const int nxt = cur ^ 1;

        // prefetch this step's xg for the finalize outputs
        float xg[4];
        if (tid < 128) {
            const float* xrow = g_xg + ((size_t)t * NB + fb) * NG + j0 + fjj;
#pragma unroll
            for (int q = 0; q < 4; q++) xg[q] = __ldg(xrow + q * 512);
        }

        // load h (L2-coherent) into padded smem
        const float4* hp = (const float4*)g_h[cur];
#pragma unroll
        for (int i = 0; i < 16; i++) {
            const int f = tid + i * SCAN_THREADS;       // 0..4095 float4s
            float4 v = __ldcg(hp + f);
            const int fi = f * 4;
            float* d = sH + (fi >> 9) * 514 + (fi & 511);
            *(float2*)d       = make_float2(v.x, v.y);
            *(float2*)(d + 2) = make_float2(v.z, v.w);
        }
        __syncthreads();

        // partial dot products over this warp's k-chunk [64w, 64w+64)
        unsigned long long acc[4][4];
#pragma unroll
        for (int ib = 0; ib < 4; ib++)
#pragma unroll
            for (int u = 0; u < 4; u++) acc[ib][u] = 0ull;

        const float* hB0 = sH + (4 * bg) * 514 + w * 64;
        const float* wB0 = sW + (4 * gg) * 514 + w * 64;

#pragma unroll 8
        for (int kp = 0; kp < 32; kp++) {
            unsigned long long h2[4], w2[4];
#pragma unroll
            for (int ib = 0; ib < 4; ib++)
                h2[ib] = *(const unsigned long long*)(hB0 + ib * 514 + 2 * kp);
#pragma unroll
            for (int u = 0; u < 4; u++)
                w2[u] = *(const unsigned long long*)(wB0 + u * 514 + 2 * kp);
#pragma unroll
            for (int ib = 0; ib < 4; ib++)
#pragma unroll
                for (int u = 0; u < 4; u++) fma2(acc[ib][u], h2[ib], w2[u]);
        }

        // bank-conflict-free partial store: column c = gg + 4*bg + 32*ib + 128*u
#pragma unroll
        for (int ib = 0; ib < 4; ib++)
#pragma unroll
            for (int u = 0; u < 4; u++) {
                float2 p = upk(acc[ib][u]);
                sRed[w * 512 + (gg + 4 * bg + 32 * ib + 128 * u)] = p.x + p.y;
            }
        __syncthreads();

        // finalize: gates -> cell update -> publish h
        if (tid < 128) {
            float gate[4];
#pragma unroll
            for (int q = 0; q < 4; q++) {
                const int c = fjj + 4 * (fb >> 2) + 32 * (fb & 3) + 128 * q;
                float s = xg[q];
#pragma unroll
                for (int ww = 0; ww < 8; ww++) s += sRed[ww * 512 + c];
                gate[q] = s;
            }
            const float ig = sigf(gate[0]);
            const float fg = sigf(gate[1]);
            const float gv = tanhf(gate[2]);
            const float og = sigf(gate[3]);
            creg = fg * creg + ig * gv;
            const float hn = og * tanhf(creg);

            const int j = j0 + fjj;
            out[((size_t)fb * NT + t) * NH + j] = hn;
            __stcg(&g_h[nxt][fb * NH + j], hn);
            if (t == NT - 1) {
                out[(size_t)NB * NT * NH + fb * NH + j] = hn;               // h_T
                out[(size_t)NB * NT * NH + NB * NH + fb * NH + j] = creg;    // c_T
            }
            __threadfence();
        }
        __syncthreads();

        // chip-wide barrier (monotonic counter, no reset race)
        if (tid == 0) {
            atomicAdd(&g_bar, 1u);
            const unsigned target = (unsigned)SCAN_BLOCKS * (unsigned)(t + 1);
            volatile unsigned* bp = &g_bar;
            while (*bp < target) { __nanosleep(32); }
            __threadfence();
        }
        __syncthreads();
    }
}

// ---------------- launch ----------------
extern "C" void kernel_launch(void* const* d_in, const int* in_sizes, int n_in,
                              void* d_out, int out_size) {
    const float* x    = (const float*)d_in[0];
    const float* Wih  = (const float*)d_in[1];
    const float* Whh  = (const float*)d_in[2];
    const float* bih  = (const float*)d_in[3];
    const float* bhh  = (const float*)d_in[4];
    float* out = (float*)d_out;

    const int scan_smem = (16 * 514 + 32 * 514 + 8 * 512) * (int)sizeof(float);
    cudaFuncSetAttribute(k_scan, cudaFuncAttributeMaxDynamicSharedMemorySize, scan_smem);

    k_init<<<16, 256>>>();

    dim3 ggrid(NG / 128, (NB * NT) / 128);   // (16, 256)
    k_gemm<<<ggrid, 256>>>(x, Wih, bih, bhh);

    k_scan<<<SCAN_BLOCKS, SCAN_THREADS, scan_smem>>>(out, Whh);
}

// round 3
// speedup vs baseline: 1.2779x; 1.2779x over previous
#include <cuda_runtime.h>
#include <cstdint>

// LSTM: B=32, T=1024, I=512, H=512, gates G=4H=2048
// out layout: outs[B][T][H] (16777216 floats) | h_T[B][H] | c_T[B][H]

#define NB 32
#define NT 1024
#define NI 512
#define NH 512
#define NG 2048

#define SCAN_BLOCKS 128
#define SCAN_THREADS 512

// ---------------- device scratch (no allocations allowed) ----------------
__device__ float g_xg[(size_t)NT * NB * NG];   // [t][b][g]  (268 MB)
__device__ float g_hT[2][NH * NB];             // TRANSPOSED hidden: [j][b], double-buffered
__device__ unsigned g_bar;                     // monotonic barrier counter

// ---------------- f32x2 helpers ----------------
__device__ __forceinline__ unsigned long long pk2(float lo, float hi) {
    unsigned long long r;
    asm("mov.b64 %0, {%1, %2};" : "=l"(r) : "f"(lo), "f"(hi));
    return r;
}
__device__ __forceinline__ void fma2(unsigned long long& acc,
                                     unsigned long long a, unsigned long long b) {
    asm("fma.rn.f32x2 %0, %1, %2, %0;" : "+l"(acc) : "l"(a), "l"(b));
}
__device__ __forceinline__ float2 upk(unsigned long long v) {
    float2 f;
    asm("mov.b64 {%0, %1}, %2;" : "=f"(f.x), "=f"(f.y) : "l"(v));
    return f;
}
__device__ __forceinline__ float sigf(float x) {
    return 1.0f / (1.0f + __expf(-x));
}

// ---------------- init: zero h0 and barrier (must run every replay) ----------------
__global__ void k_init() {
    int t = threadIdx.x + blockIdx.x * blockDim.x;
    if (t == 0) g_bar = 0u;
    for (int i = t; i < NH * NB; i += gridDim.x * blockDim.x) {
        g_hT[0][i] = 0.0f;
        g_hT[1][i] = 0.0f;
    }
}

// ---------------- GEMM: xg[t][b][g] = x[b][t][:] . W_ih[g][:] + b_ih[g] + b_hh[g] ----------------
// (unchanged from round 1: 128x128x16 tiles, double-buffered smem, f32x2)
__global__ void __launch_bounds__(256) k_gemm(const float* __restrict__ X,
                                              const float* __restrict__ Wih,
                                              const float* __restrict__ bih,
                                              const float* __restrict__ bhh) {
    __shared__ float As[2][16][132];
    __shared__ float Bs[2][16][132];

    const int tid = threadIdx.x;
    const int m0 = blockIdx.y * 128;
    const int n0 = blockIdx.x * 128;
    const int tx = tid & 15;
    const int ty = tid >> 4;
    const int lr = tid >> 2;
    const int lq = tid & 3;

    unsigned long long acc[8][4];
#pragma unroll
    for (int i = 0; i < 8; i++)
#pragma unroll
        for (int j = 0; j < 4; j++) acc[i][j] = 0ull;

    float4 aR[2], bR[2];

#pragma unroll
    for (int l = 0; l < 2; l++) {
        aR[l] = __ldg((const float4*)(X   + (size_t)(m0 + lr + 64 * l) * NI + 4 * lq));
        bR[l] = __ldg((const float4*)(Wih + (size_t)(n0 + lr + 64 * l) * NI + 4 * lq));
    }

    int buf = 0;
    for (int it = 0; it < 32; it++) {
#pragma unroll
        for (int l = 0; l < 2; l++) {
            const float* av = (const float*)&aR[l];
            const float* bv = (const float*)&bR[l];
#pragma unroll
            for (int i = 0; i < 4; i++) {
                As[buf][4 * lq + i][lr + 64 * l] = av[i];
                Bs[buf][4 * lq + i][lr + 64 * l] = bv[i];
            }
        }
        __syncthreads();

        if (it < 31) {
            const int k0 = (it + 1) * 16;
#pragma unroll
            for (int l = 0; l < 2; l++) {
                aR[l] = __ldg((const float4*)(X   + (size_t)(m0 + lr + 64 * l) * NI + k0 + 4 * lq));
                bR[l] = __ldg((const float4*)(Wih + (size_t)(n0 + lr + 64 * l) * NI + k0 + 4 * lq));
            }
        }

#pragma unroll
        for (int k = 0; k < 16; k++) {
            float4 a0 = *(const float4*)&As[buf][k][ty * 8];
            float4 a1 = *(const float4*)&As[buf][k][ty * 8 + 4];
            float4 b0 = *(const float4*)&Bs[buf][k][tx * 8];
            float4 b1 = *(const float4*)&Bs[buf][k][tx * 8 + 4];
            unsigned long long bb[4] = {pk2(b0.x, b0.y), pk2(b0.z, b0.w),
                                        pk2(b1.x, b1.y), pk2(b1.z, b1.w)};
            float av[8] = {a0.x, a0.y, a0.z, a0.w, a1.x, a1.y, a1.z, a1.w};
#pragma unroll
            for (int i = 0; i < 8; i++) {
                unsigned long long aa = pk2(av[i], av[i]);
#pragma unroll
                for (int j = 0; j < 4; j++) fma2(acc[i][j], aa, bb[j]);
            }
        }
        buf ^= 1;
        __syncthreads();
    }

    const int nb = n0 + tx * 8;
    float bias[8];
#pragma unroll
    for (int j = 0; j < 8; j++) bias[j] = __ldg(bih + nb + j) + __ldg(bhh + nb + j);

#pragma unroll
    for (int i = 0; i < 8; i++) {
        const int m = m0 + ty * 8 + i;
        const int t = m & (NT - 1);
        const int b = m >> 10;
        float* orow = g_xg + ((size_t)t * NB + b) * NG + nb;
#pragma unroll
        for (int j2 = 0; j2 < 4; j2++) {
            float2 v = upk(acc[i][j2]);
            v.x += bias[2 * j2];
            v.y += bias[2 * j2 + 1];
            *(float2*)(orow + 2 * j2) = v;
        }
    }
}

// ---------------- persistent scan kernel (v2) ----------------
// 128 blocks x 512 threads; block bid owns hidden units j0 = bid*4..+3
// (16 gate rows: grow(gl) = (gl&3)*512 + j0 + (gl>>2), gl = 4*unit + gate).
//
// Per step:
//   - h is read DIRECTLY from global (transposed layout g_hT[j][b]) as
//     coalesced LDG.128 per warp K-chunk — no smem staging, no transpose.
//   - W_hh lives in smem pre-duplicated as f32x2 (w,w) pairs: 2 conflict-free
//     broadcast LDS.128 + 8 FMA2 per k.
//   - 16 warps split K (32 each); partials -> sRed[16][512]; 512-thread
//     pre-reduce -> sFin[512]; 128-thread finalize (c in regs).
//   - one chip-wide monotonic-counter barrier per step.
__global__ void __launch_bounds__(SCAN_THREADS, 1) k_scan(float* __restrict__ out,
                                                          const float* __restrict__ Whh) {
    extern __shared__ float sm[];
    unsigned long long* sWT2 = (unsigned long long*)sm;       // [512][16] ull pairs (64 KB)
    float* sRed = (float*)(sWT2 + 512 * 16);                  // [16][512]
    float* sFin = sRed + 16 * 512;                            // [512]

    const int tid = threadIdx.x;
    const int bid = blockIdx.x;
    const int j0 = bid * 4;

    // Load this block's 16 W_hh rows into smem, duplicated as (w,w) pairs.
    for (int idx = tid; idx < 16 * 512; idx += SCAN_THREADS) {
        const int gl = idx & 15;
        const int k  = idx >> 4;
        const int grow = (gl & 3) * 512 + j0 + (gl >> 2);
        const float wv = __ldg(Whh + (size_t)grow * NH + k);
        sWT2[(size_t)k * 16 + gl] = pk2(wv, wv);
    }

    // dot-phase roles
    const int w    = tid >> 5;        // K-chunk (warp), 0..15, k in [32w, 32w+32)
    const int lane = tid & 31;
    const int bg   = lane & 7;        // b group: b = 4*bg + ib
    const int gg   = lane >> 3;       // unit group: gl = 4*gg + u

    // finalize roles (tid < 128)
    const int fb  = tid & 31;
    const int fjj = tid >> 5;

    float creg = 0.0f;
    __syncthreads();

    for (int t = 0; t < NT; t++) {
        const int cur = t & 1;
        const int nxt = cur ^ 1;

        // prefetch this step's xg (DRAM, long latency — issue first)
        float xg[4];
        if (tid < 128) {
            const float* xrow = g_xg + ((size_t)t * NB + fb) * NG + j0 + fjj;
#pragma unroll
            for (int q = 0; q < 4; q++) xg[q] = __ldcg(xrow + q * 512);
        }

        // ---- dot phase: h straight from global (coalesced, L2-coherent) ----
        unsigned long long acc[2][4];
#pragma unroll
        for (int bp = 0; bp < 2; bp++)
#pragma unroll
            for (int u = 0; u < 4; u++) acc[bp][u] = 0ull;

        const float* hk = g_hT[cur] + (w * 32) * NB + 4 * bg;  // k*32 + 4*bg

        ulonglong2 hb[2][8];
#pragma unroll
        for (int i = 0; i < 8; i++)
            hb[0][i] = __ldcg((const ulonglong2*)(hk + i * NB));

        int pb = 0;
#pragma unroll
        for (int gq = 0; gq < 4; gq++) {
            if (gq < 3) {
#pragma unroll
                for (int i = 0; i < 8; i++)
                    hb[pb ^ 1][i] = __ldcg((const ulonglong2*)(hk + (8 * (gq + 1) + i) * NB));
            }
#pragma unroll
            for (int i = 0; i < 8; i++) {
                const int k = 32 * w + 8 * gq + i;
                const ulonglong2* wp = (const ulonglong2*)(sWT2 + (size_t)k * 16 + 4 * gg);
                ulonglong2 w01 = wp[0];
                ulonglong2 w23 = wp[1];
                const unsigned long long hlo = hb[pb][i].x;   // b = 4bg+0,1
                const unsigned long long hhi = hb[pb][i].y;   // b = 4bg+2,3
                fma2(acc[0][0], hlo, w01.x);
                fma2(acc[0][1], hlo, w01.y);
                fma2(acc[0][2], hlo, w23.x);
                fma2(acc[0][3], hlo, w23.y);
                fma2(acc[1][0], hhi, w01.x);
                fma2(acc[1][1], hhi, w01.y);
                fma2(acc[1][2], hhi, w23.x);
                fma2(acc[1][3], hhi, w23.y);
            }
            pb ^= 1;
        }

        // partial store: col = gg + 4*bg + 32*ib + 128*u  (conflict-free)
#pragma unroll
        for (int bp = 0; bp < 2; bp++)
#pragma unroll
            for (int u = 0; u < 4; u++) {
                float2 p = upk(acc[bp][u]);
                sRed[w * 512 + (gg + 4 * bg + 32 * (2 * bp + 0) + 128 * u)] = p.x;
                sRed[w * 512 + (gg + 4 * bg + 32 * (2 * bp + 1) + 128 * u)] = p.y;
            }
        __syncthreads();

        // ---- pre-reduce: all 512 threads, one column each ----
        {
            float s = sRed[tid];
#pragma unroll
            for (int r = 1; r < 16; r++) s += sRed[r * 512 + tid];
            sFin[tid] = s;
        }
        __syncthreads();

        // ---- finalize: gates -> cell update -> publish h ----
        if (tid < 128) {
            float gate[4];
#pragma unroll
            for (int q = 0; q < 4; q++) {
                const int c = fjj + 4 * (fb >> 2) + 32 * (fb & 3) + 128 * q;
                gate[q] = xg[q] + sFin[c];
            }
            const float ig = sigf(gate[0]);
            const float fg = sigf(gate[1]);
            const float gv = tanhf(gate[2]);
            const float og = sigf(gate[3]);
            creg = fg * creg + ig * gv;
            const float hn = og * tanhf(creg);

            const int j = j0 + fjj;
            out[((size_t)fb * NT + t) * NH + j] = hn;
            __stcg(&g_hT[nxt][j * NB + fb], hn);          // coalesced over fb
            if (t == NT - 1) {
                out[(size_t)NB * NT * NH + fb * NH + j] = hn;                // h_T
                out[(size_t)NB * NT * NH + NB * NH + fb * NH + j] = creg;    // c_T
            }
        }
        __syncthreads();

        // ---- chip-wide barrier (monotonic counter; tid0 fence pattern) ----
        if (tid == 0) {
            __threadfence();   // cumulative: orders all block stores before arrive
            atomicAdd(&g_bar, 1u);
            const unsigned target = (unsigned)SCAN_BLOCKS * (unsigned)(t + 1);
            volatile unsigned* bp2 = &g_bar;
            while (*bp2 < target) { __nanosleep(32); }
            __threadfence();   // acquire side
        }
        __syncthreads();
    }
}

// ---------------- launch ----------------
extern "C" void kernel_launch(void* const* d_in, const int* in_sizes, int n_in,
                              void* d_out, int out_size) {
    const float* x    = (const float*)d_in[0];
    const float* Wih  = (const float*)d_in[1];
    const float* Whh  = (const float*)d_in[2];
    const float* bih  = (const float*)d_in[3];
    const float* bhh  = (const float*)d_in[4];
    float* out = (float*)d_out;

    const int scan_smem = 512 * 16 * 8 + 16 * 512 * 4 + 512 * 4;  // 100,352 B
    cudaFuncSetAttribute(k_scan, cudaFuncAttributeMaxDynamicSharedMemorySize, scan_smem);

    k_init<<<16, 256>>>();

    dim3 ggrid(NG / 128, (NB * NT) / 128);   // (16, 256)
    k_gemm<<<ggrid, 256>>>(x, Wih, bih, bhh);

    k_scan<<<SCAN_BLOCKS, SCAN_THREADS, scan_smem>>>(out, Whh);
}